// round 14
// baseline (speedup 1.0000x reference)
#include <cuda_runtime.h>
#include <math.h>

// Problem constants
#define BB   8
#define TT   12
#define HWD  96
#define CIN  32
#define COUT 128
#define PIX  (HWD*HWD)          // 9216
#define NTH  256

// ---------------- device scratch (no allocs allowed) ----------------
// Z[t][b][pix][128] : precomputed conv(x_t, Wx) + bias, fp32
__device__ __align__(16) float g_Z[(size_t)TT * BB * PIX * COUT];   // ~453 MB
// h ping-pong buffers [2][b][pix][32]
__device__ __align__(16) float g_H[2][BB * PIX * CIN];
// c state (in-place per element is race-free: each element touched by one thread)
__device__ __align__(16) float g_C[BB * PIX * CIN];
// combined recurrent weight Wc = Wx + Wh : [3][3][32][128]
__device__ __align__(16) float g_Wc[9 * CIN * COUT];

__device__ __forceinline__ float hsig(float z) {
    return fminf(fmaxf(fmaf(z, 0.2f, 0.5f), 0.0f), 1.0f);
}

// ---------------- tiny kernel: Wc = Wx + Wh ----------------
__global__ void wcombine_kernel(const float* __restrict__ Wx,
                                const float* __restrict__ Wh) {
    int i = blockIdx.x * NTH + threadIdx.x;
    if (i < 9 * CIN * COUT) g_Wc[i] = Wx[i] + Wh[i];
}

// ---------------- step 0: gates on Z[0] with h=c=0 ----------------
__global__ void gate0_kernel(float* __restrict__ dout) {
    int idx = blockIdx.x * NTH + threadIdx.x;     // < BB*PIX*CIN
    int f    = idx & 31;
    int rest = idx >> 5;                           // b*PIX + pix
    int pix  = rest % PIX;
    int b    = rest / PIX;
    const float* Z0 = g_Z + ((size_t)b * PIX + pix) * COUT;
    float zi = Z0[f], zf = Z0[32 + f], zc = Z0[64 + f], zo = Z0[96 + f];
    float cn = hsig(zi) * tanhf(zc);               // f*0 + i*tanh(zc)
    float hn = hsig(zo) * tanhf(cn);
    int hoff = (b * PIX + pix) * CIN + f;
    g_C[hoff]    = cn;
    g_H[0][hoff] = hn;
    dout[(size_t)b * (TT * PIX * CIN) + (size_t)pix * CIN + f] = hn;  // t=0 slice
}

// ---------------- main conv kernel ----------------
// Block: 8x8 pixel tile x all 128 out channels. 256 threads:
//   thread = (pg = tid>>4 : 16 pixel groups of 4 px) x (pc = tid&15 : 16 oc groups of 8)
// smem: in_s[32][10][10] (transposed, halo) | w_s[3][32][128] (per-ky stage) | zs[64][128] (RECUR)
template<bool RECUR>
__global__ void __launch_bounds__(NTH, 2) conv_kernel(
    const float* __restrict__ xin,    // tensor base (precompute); unused if RECUR
    const float* __restrict__ wsrc,   // Wx (precompute); unused if RECUR (uses g_Wc)
    const float* __restrict__ bias,   // bias (precompute); unused if RECUR
    float* __restrict__ dout,         // output (RECUR); unused otherwise
    int t)                            // step (RECUR)
{
    extern __shared__ float smem[];
    float* in_s = smem;                       // 3200 floats
    float* w_s  = smem + 3200;                // 12288 floats
    float* zs   = smem + 3200 + 12288;        // 8192 floats (RECUR only)

    const int tid   = threadIdx.x;
    const int tileY = blockIdx.x / 12, tileX = blockIdx.x % 12;
    const int y0 = tileY * 8, x0t = tileX * 8;

    int b;
    const float* src;
    const float* wg;
    if (RECUR) {
        b   = blockIdx.y;
        src = g_H[(t - 1) & 1] + (size_t)b * PIX * CIN;   // read previous h
        wg  = g_Wc;
    } else {
        int m = blockIdx.y;                   // m = b*TT + t  (tensor layout [b][t])
        src = xin + (size_t)m * PIX * CIN;
        b   = m / TT;
        wg  = wsrc;
    }

    // ---- load input tile with halo, transposed to [ic][yy][xx] ----
    for (int i = tid; i < 3200; i += NTH) {
        int ic = i & 31, pos = i >> 5;        // 100 positions of 10x10 halo
        int yy = pos / 10, xx = pos - yy * 10;
        int gy = y0 + yy - 1, gx = x0t + xx - 1;
        float v = 0.0f;
        if ((unsigned)gy < (unsigned)HWD && (unsigned)gx < (unsigned)HWD)
            v = src[(gy * HWD + gx) * CIN + ic];
        in_s[ic * 100 + pos] = v;
    }

    const int pg  = tid >> 4, pc = tid & 15;
    const int py  = pg >> 1,  px0 = (pg & 1) * 4;
    const int oc0 = pc * 8;

    float acc[4][8];
    if (RECUR) {
        const float* Zt = g_Z + ((size_t)(t * BB + b) * PIX) * COUT;
        #pragma unroll
        for (int p = 0; p < 4; p++) {
            int pix = (y0 + py) * HWD + x0t + px0 + p;
            const float4* zp = (const float4*)(Zt + (size_t)pix * COUT + oc0);
            float4 a0 = zp[0], a1 = zp[1];
            acc[p][0] = a0.x; acc[p][1] = a0.y; acc[p][2] = a0.z; acc[p][3] = a0.w;
            acc[p][4] = a1.x; acc[p][5] = a1.y; acc[p][6] = a1.z; acc[p][7] = a1.w;
        }
    } else {
        float bv[8];
        #pragma unroll
        for (int q = 0; q < 8; q++) bv[q] = bias[oc0 + q];
        #pragma unroll
        for (int p = 0; p < 4; p++)
            #pragma unroll
            for (int q = 0; q < 8; q++) acc[p][q] = bv[q];
    }

    // ---- main loop: ky outer (stage 49KB of weights), then ic, kx ----
    for (int ky = 0; ky < 3; ky++) {
        __syncthreads();
        {
            const float4* wsrc4 = (const float4*)(wg + (size_t)ky * 12288);
            float4* wdst4 = (float4*)w_s;
            for (int i = tid; i < 3072; i += NTH) wdst4[i] = wsrc4[i];
        }
        __syncthreads();

        const float* irow = in_s + (py + ky) * 10 + px0;
        #pragma unroll 2
        for (int ic = 0; ic < 32; ic++) {
            float r[6];
            const float* ir = irow + ic * 100;
            #pragma unroll
            for (int j = 0; j < 6; j++) r[j] = ir[j];
            #pragma unroll
            for (int kx = 0; kx < 3; kx++) {
                const float4* wp = (const float4*)(w_s + (kx * 32 + ic) * COUT + oc0);
                float4 w0 = wp[0], w1 = wp[1];
                float w[8] = {w0.x, w0.y, w0.z, w0.w, w1.x, w1.y, w1.z, w1.w};
                #pragma unroll
                for (int p = 0; p < 4; p++) {
                    float rv = r[kx + p];
                    #pragma unroll
                    for (int q = 0; q < 8; q++)
                        acc[p][q] = fmaf(rv, w[q], acc[p][q]);
                }
            }
        }
    }

    if (!RECUR) {
        // store z-tile to Z[t][b]
        int m = blockIdx.y; int bb = m / TT, tt = m - bb * TT;
        float* Zt = g_Z + ((size_t)(tt * BB + bb) * PIX) * COUT;
        #pragma unroll
        for (int p = 0; p < 4; p++) {
            int pix = (y0 + py) * HWD + x0t + px0 + p;
            float4* zp = (float4*)(Zt + (size_t)pix * COUT + oc0);
            zp[0] = make_float4(acc[p][0], acc[p][1], acc[p][2], acc[p][3]);
            zp[1] = make_float4(acc[p][4], acc[p][5], acc[p][6], acc[p][7]);
        }
    } else {
        // exchange z through smem, then fused LSTM gate epilogue
        #pragma unroll
        for (int p = 0; p < 4; p++) {
            int lp = py * 8 + px0 + p;
            float4* zp = (float4*)(zs + lp * COUT + oc0);
            zp[0] = make_float4(acc[p][0], acc[p][1], acc[p][2], acc[p][3]);
            zp[1] = make_float4(acc[p][4], acc[p][5], acc[p][6], acc[p][7]);
        }
        __syncthreads();

        float* Hcur = g_H[t & 1];
        #pragma unroll
        for (int k = 0; k < 8; k++) {
            int idx = tid + k * NTH;          // 2048 (px,f) pairs
            int f  = idx & 31, lp = idx >> 5;
            float zi = zs[lp * COUT + f];
            float zf = zs[lp * COUT + 32 + f];
            float zc = zs[lp * COUT + 64 + f];
            float zo = zs[lp * COUT + 96 + f];
            int ly = lp >> 3, lx = lp & 7;
            int gy = y0 + ly, gx = x0t + lx;
            int hoff = (b * PIX + gy * HWD + gx) * CIN + f;
            float cold = g_C[hoff];
            float cn = hsig(zf) * cold + hsig(zi) * tanhf(zc);
            float hn = hsig(zo) * tanhf(cn);
            g_C[hoff]  = cn;
            Hcur[hoff] = hn;
            dout[(size_t)b * (TT * PIX * CIN) + (size_t)t * (PIX * CIN)
                 + (size_t)(gy * HWD + gx) * CIN + f] = hn;
        }
    }
}

// ---------------- launch ----------------
extern "C" void kernel_launch(void* const* d_in, const int* in_sizes, int n_in,
                              void* d_out, int out_size) {
    (void)in_sizes; (void)n_in; (void)out_size;
    const float* tensor = (const float*)d_in[0];   // (8,12,96,96,32)
    const float* Wx     = (const float*)d_in[1];   // (3,3,32,128)
    const float* Wh     = (const float*)d_in[2];   // (3,3,32,128)
    const float* bias   = (const float*)d_in[3];   // (128,)
    float* out = (float*)d_out;                    // (8,12,1,96,96,32) fp32

    const int SMEM_PRE = (3200 + 12288) * 4;          // 61952 B
    const int SMEM_REC = (3200 + 12288 + 8192) * 4;   // 94720 B
    cudaFuncSetAttribute((const void*)conv_kernel<false>,
                         cudaFuncAttributeMaxDynamicSharedMemorySize, SMEM_PRE);
    cudaFuncSetAttribute((const void*)conv_kernel<true>,
                         cudaFuncAttributeMaxDynamicSharedMemorySize, SMEM_REC);

    // 1) combined recurrent weights
    wcombine_kernel<<<(9 * CIN * COUT + NTH - 1) / NTH, NTH>>>(Wx, Wh);

    // 2) precompute Z[t] = conv(x_t, Wx) + b for all 96 (b,t) images in parallel
    conv_kernel<false><<<dim3(144, BB * TT), NTH, SMEM_PRE>>>(tensor, Wx, bias, nullptr, 0);

    // 3) step 0: h=c=0 -> pure pointwise gates on Z[0]
    gate0_kernel<<<(BB * PIX * CIN) / NTH, NTH>>>(out);

    // 4) steps 1..11: z = Z[t] + conv(h_{t-1}, Wc), fused gate update
    for (int t = 1; t < TT; t++)
        conv_kernel<true><<<dim3(144, BB), NTH, SMEM_REC>>>(nullptr, nullptr, nullptr, out, t);
}

// round 15
// speedup vs baseline: 1.0013x; 1.0013x over previous
#include <cuda_runtime.h>
#include <math.h>

// Problem constants
#define BB   8
#define TT   12
#define HWD  96
#define CIN  32
#define COUT 128
#define PIX  (HWD*HWD)          // 9216
#define NTH  256

// ---------------- device scratch (no allocs allowed) ----------------
// Z[t][b][pix][128] : precomputed conv(x_t, Wx) + bias, fp32
__device__ __align__(16) float g_Z[(size_t)TT * BB * PIX * COUT];   // ~453 MB
// h ping-pong buffers [2][b][pix][32]
__device__ __align__(16) float g_H[2][BB * PIX * CIN];
// c state (in-place per element is race-free: each element touched by one thread)
__device__ __align__(16) float g_C[BB * PIX * CIN];
// combined recurrent weight Wc = Wx + Wh : [3][3][32][128]
__device__ __align__(16) float g_Wc[9 * CIN * COUT];

__device__ __forceinline__ float hsig(float z) {
    return fminf(fmaxf(fmaf(z, 0.2f, 0.5f), 0.0f), 1.0f);
}

// ---------------- tiny kernel: Wc = Wx + Wh ----------------
__global__ void wcombine_kernel(const float* __restrict__ Wx,
                                const float* __restrict__ Wh) {
    int i = blockIdx.x * NTH + threadIdx.x;
    if (i < 9 * CIN * COUT) g_Wc[i] = Wx[i] + Wh[i];
}

// ---------------- step 0: gates on Z[0] with h=c=0 ----------------
__global__ void gate0_kernel(float* __restrict__ dout) {
    int idx = blockIdx.x * NTH + threadIdx.x;     // < BB*PIX*CIN
    int f    = idx & 31;
    int rest = idx >> 5;                           // b*PIX + pix
    int pix  = rest % PIX;
    int b    = rest / PIX;
    const float* Z0 = g_Z + ((size_t)b * PIX + pix) * COUT;
    float zi = Z0[f], zf = Z0[32 + f], zc = Z0[64 + f], zo = Z0[96 + f];
    float cn = hsig(zi) * tanhf(zc);               // f*0 + i*tanh(zc)
    float hn = hsig(zo) * tanhf(cn);
    int hoff = (b * PIX + pix) * CIN + f;
    g_C[hoff]    = cn;
    g_H[0][hoff] = hn;
    dout[(size_t)b * (TT * PIX * CIN) + (size_t)pix * CIN + f] = hn;  // t=0 slice
}

// ---------------- main conv kernel ----------------
// Block: 8x8 pixel tile x all 128 out channels. 256 threads:
//   thread = (pg = tid>>4 : 16 pixel groups of 4 px) x (pc = tid&15 : 16 oc groups of 8)
// smem: in_s[32][10][10] (transposed, halo) | w_s[3][32][128] (per-ky stage) | zs[64][128] (RECUR)
template<bool RECUR>
__global__ void __launch_bounds__(NTH, 2) conv_kernel(
    const float* __restrict__ xin,    // tensor base (precompute); unused if RECUR
    const float* __restrict__ wsrc,   // Wx (precompute); unused if RECUR (uses g_Wc)
    const float* __restrict__ bias,   // bias (precompute); unused if RECUR
    float* __restrict__ dout,         // output (RECUR); unused otherwise
    int t)                            // step (RECUR)
{
    extern __shared__ float smem[];
    float* in_s = smem;                       // 3200 floats
    float* w_s  = smem + 3200;                // 12288 floats
    float* zs   = smem + 3200 + 12288;        // 8192 floats (RECUR only)

    const int tid   = threadIdx.x;
    const int tileY = blockIdx.x / 12, tileX = blockIdx.x % 12;
    const int y0 = tileY * 8, x0t = tileX * 8;

    int b;
    const float* src;
    const float* wg;
    if (RECUR) {
        b   = blockIdx.y;
        src = g_H[(t - 1) & 1] + (size_t)b * PIX * CIN;   // read previous h
        wg  = g_Wc;
    } else {
        int m = blockIdx.y;                   // m = b*TT + t  (tensor layout [b][t])
        src = xin + (size_t)m * PIX * CIN;
        b   = m / TT;
        wg  = wsrc;
    }

    // ---- load input tile with halo, transposed to [ic][yy][xx] ----
    for (int i = tid; i < 3200; i += NTH) {
        int ic = i & 31, pos = i >> 5;        // 100 positions of 10x10 halo
        int yy = pos / 10, xx = pos - yy * 10;
        int gy = y0 + yy - 1, gx = x0t + xx - 1;
        float v = 0.0f;
        if ((unsigned)gy < (unsigned)HWD && (unsigned)gx < (unsigned)HWD)
            v = src[(gy * HWD + gx) * CIN + ic];
        in_s[ic * 100 + pos] = v;
    }

    const int pg  = tid >> 4, pc = tid & 15;
    const int py  = pg >> 1,  px0 = (pg & 1) * 4;
    const int oc0 = pc * 8;

    float acc[4][8];
    if (RECUR) {
        const float* Zt = g_Z + ((size_t)(t * BB + b) * PIX) * COUT;
        #pragma unroll
        for (int p = 0; p < 4; p++) {
            int pix = (y0 + py) * HWD + x0t + px0 + p;
            const float4* zp = (const float4*)(Zt + (size_t)pix * COUT + oc0);
            float4 a0 = zp[0], a1 = zp[1];
            acc[p][0] = a0.x; acc[p][1] = a0.y; acc[p][2] = a0.z; acc[p][3] = a0.w;
            acc[p][4] = a1.x; acc[p][5] = a1.y; acc[p][6] = a1.z; acc[p][7] = a1.w;
        }
    } else {
        float bv[8];
        #pragma unroll
        for (int q = 0; q < 8; q++) bv[q] = bias[oc0 + q];
        #pragma unroll
        for (int p = 0; p < 4; p++)
            #pragma unroll
            for (int q = 0; q < 8; q++) acc[p][q] = bv[q];
    }

    // ---- main loop: ky outer (stage 49KB of weights), then ic, kx ----
    for (int ky = 0; ky < 3; ky++) {
        __syncthreads();
        {
            const float4* wsrc4 = (const float4*)(wg + (size_t)ky * 12288);
            float4* wdst4 = (float4*)w_s;
            for (int i = tid; i < 3072; i += NTH) wdst4[i] = wsrc4[i];
        }
        __syncthreads();

        const float* irow = in_s + (py + ky) * 10 + px0;
        #pragma unroll 2
        for (int ic = 0; ic < 32; ic++) {
            float r[6];
            const float* ir = irow + ic * 100;
            #pragma unroll
            for (int j = 0; j < 6; j++) r[j] = ir[j];
            #pragma unroll
            for (int kx = 0; kx < 3; kx++) {
                const float4* wp = (const float4*)(w_s + (kx * 32 + ic) * COUT + oc0);
                float4 w0 = wp[0], w1 = wp[1];
                float w[8] = {w0.x, w0.y, w0.z, w0.w, w1.x, w1.y, w1.z, w1.w};
                #pragma unroll
                for (int p = 0; p < 4; p++) {
                    float rv = r[kx + p];
                    #pragma unroll
                    for (int q = 0; q < 8; q++)
                        acc[p][q] = fmaf(rv, w[q], acc[p][q]);
                }
            }
        }
    }

    if (!RECUR) {
        // store z-tile to Z[t][b]
        int m = blockIdx.y; int bb = m / TT, tt = m - bb * TT;
        float* Zt = g_Z + ((size_t)(tt * BB + bb) * PIX) * COUT;
        #pragma unroll
        for (int p = 0; p < 4; p++) {
            int pix = (y0 + py) * HWD + x0t + px0 + p;
            float4* zp = (float4*)(Zt + (size_t)pix * COUT + oc0);
            zp[0] = make_float4(acc[p][0], acc[p][1], acc[p][2], acc[p][3]);
            zp[1] = make_float4(acc[p][4], acc[p][5], acc[p][6], acc[p][7]);
        }
    } else {
        // exchange z through smem, then fused LSTM gate epilogue
        #pragma unroll
        for (int p = 0; p < 4; p++) {
            int lp = py * 8 + px0 + p;
            float4* zp = (float4*)(zs + lp * COUT + oc0);
            zp[0] = make_float4(acc[p][0], acc[p][1], acc[p][2], acc[p][3]);
            zp[1] = make_float4(acc[p][4], acc[p][5], acc[p][6], acc[p][7]);
        }
        __syncthreads();

        float* Hcur = g_H[t & 1];
        #pragma unroll
        for (int k = 0; k < 8; k++) {
            int idx = tid + k * NTH;          // 2048 (px,f) pairs
            int f  = idx & 31, lp = idx >> 5;
            float zi = zs[lp * COUT + f];
            float zf = zs[lp * COUT + 32 + f];
            float zc = zs[lp * COUT + 64 + f];
            float zo = zs[lp * COUT + 96 + f];
            int ly = lp >> 3, lx = lp & 7;
            int gy = y0 + ly, gx = x0t + lx;
            int hoff = (b * PIX + gy * HWD + gx) * CIN + f;
            float cold = g_C[hoff];
            float cn = hsig(zf) * cold + hsig(zi) * tanhf(zc);
            float hn = hsig(zo) * tanhf(cn);
            g_C[hoff]  = cn;
            Hcur[hoff] = hn;
            dout[(size_t)b * (TT * PIX * CIN) + (size_t)t * (PIX * CIN)
                 + (size_t)(gy * HWD + gx) * CIN + f] = hn;
        }
    }
}

// ---------------- launch ----------------
extern "C" void kernel_launch(void* const* d_in, const int* in_sizes, int n_in,
                              void* d_out, int out_size) {
    (void)in_sizes; (void)n_in; (void)out_size;
    const float* tensor = (const float*)d_in[0];   // (8,12,96,96,32)
    const float* Wx     = (const float*)d_in[1];   // (3,3,32,128)
    const float* Wh     = (const float*)d_in[2];   // (3,3,32,128)
    const float* bias   = (const float*)d_in[3];   // (128,)
    float* out = (float*)d_out;                    // (8,12,1,96,96,32) fp32

    const int SMEM_PRE = (3200 + 12288) * 4;          // 61952 B
    const int SMEM_REC = (3200 + 12288 + 8192) * 4;   // 94720 B
    cudaFuncSetAttribute((const void*)conv_kernel<false>,
                         cudaFuncAttributeMaxDynamicSharedMemorySize, SMEM_PRE);
    cudaFuncSetAttribute((const void*)conv_kernel<true>,
                         cudaFuncAttributeMaxDynamicSharedMemorySize, SMEM_REC);

    // 1) combined recurrent weights
    wcombine_kernel<<<(9 * CIN * COUT + NTH - 1) / NTH, NTH>>>(Wx, Wh);

    // 2) precompute Z[t] = conv(x_t, Wx) + b for all 96 (b,t) images in parallel
    conv_kernel<false><<<dim3(144, BB * TT), NTH, SMEM_PRE>>>(tensor, Wx, bias, nullptr, 0);

    // 3) step 0: h=c=0 -> pure pointwise gates on Z[0]
    gate0_kernel<<<(BB * PIX * CIN) / NTH, NTH>>>(out);

    // 4) steps 1..11: z = Z[t] + conv(h_{t-1}, Wc), fused gate update
    for (int t = 1; t < TT; t++)
        conv_kernel<true><<<dim3(144, BB), NTH, SMEM_REC>>>(nullptr, nullptr, nullptr, out, t);
}

// round 16
// speedup vs baseline: 1.0014x; 1.0001x over previous
#include <cuda_runtime.h>
#include <math.h>

// Problem constants
#define BB   8
#define TT   12
#define HWD  96
#define CIN  32
#define COUT 128
#define PIX  (HWD*HWD)          // 9216
#define NTH  256

// ---------------- device scratch (no allocs allowed) ----------------
// Z[t][b][pix][128] : precomputed conv(x_t, Wx) + bias, fp32
__device__ __align__(16) float g_Z[(size_t)TT * BB * PIX * COUT];   // ~453 MB
// h ping-pong buffers [2][b][pix][32]
__device__ __align__(16) float g_H[2][BB * PIX * CIN];
// c state (in-place per element is race-free: each element touched by one thread)
__device__ __align__(16) float g_C[BB * PIX * CIN];
// combined recurrent weight Wc = Wx + Wh : [3][3][32][128]
__device__ __align__(16) float g_Wc[9 * CIN * COUT];

__device__ __forceinline__ float hsig(float z) {
    return fminf(fmaxf(fmaf(z, 0.2f, 0.5f), 0.0f), 1.0f);
}

// ---------------- tiny kernel: Wc = Wx + Wh ----------------
__global__ void wcombine_kernel(const float* __restrict__ Wx,
                                const float* __restrict__ Wh) {
    int i = blockIdx.x * NTH + threadIdx.x;
    if (i < 9 * CIN * COUT) g_Wc[i] = Wx[i] + Wh[i];
}

// ---------------- step 0: gates on Z[0] with h=c=0 ----------------
__global__ void gate0_kernel(float* __restrict__ dout) {
    int idx = blockIdx.x * NTH + threadIdx.x;     // < BB*PIX*CIN
    int f    = idx & 31;
    int rest = idx >> 5;                           // b*PIX + pix
    int pix  = rest % PIX;
    int b    = rest / PIX;
    const float* Z0 = g_Z + ((size_t)b * PIX + pix) * COUT;
    float zi = Z0[f], zf = Z0[32 + f], zc = Z0[64 + f], zo = Z0[96 + f];
    float cn = hsig(zi) * tanhf(zc);               // f*0 + i*tanh(zc)
    float hn = hsig(zo) * tanhf(cn);
    int hoff = (b * PIX + pix) * CIN + f;
    g_C[hoff]    = cn;
    g_H[0][hoff] = hn;
    dout[(size_t)b * (TT * PIX * CIN) + (size_t)pix * CIN + f] = hn;  // t=0 slice
}

// ---------------- main conv kernel ----------------
// Block: 8x8 pixel tile x all 128 out channels. 256 threads:
//   thread = (pg = tid>>4 : 16 pixel groups of 4 px) x (pc = tid&15 : 16 oc groups of 8)
// smem: in_s[32][10][10] (transposed, halo) | w_s[3][32][128] (per-ky stage) | zs[64][128] (RECUR)
template<bool RECUR>
__global__ void __launch_bounds__(NTH, 2) conv_kernel(
    const float* __restrict__ xin,    // tensor base (precompute); unused if RECUR
    const float* __restrict__ wsrc,   // Wx (precompute); unused if RECUR (uses g_Wc)
    const float* __restrict__ bias,   // bias (precompute); unused if RECUR
    float* __restrict__ dout,         // output (RECUR); unused otherwise
    int t)                            // step (RECUR)
{
    extern __shared__ float smem[];
    float* in_s = smem;                       // 3200 floats
    float* w_s  = smem + 3200;                // 12288 floats
    float* zs   = smem + 3200 + 12288;        // 8192 floats (RECUR only)

    const int tid   = threadIdx.x;
    const int tileY = blockIdx.x / 12, tileX = blockIdx.x % 12;
    const int y0 = tileY * 8, x0t = tileX * 8;

    int b;
    const float* src;
    const float* wg;
    if (RECUR) {
        b   = blockIdx.y;
        src = g_H[(t - 1) & 1] + (size_t)b * PIX * CIN;   // read previous h
        wg  = g_Wc;
    } else {
        int m = blockIdx.y;                   // m = b*TT + t  (tensor layout [b][t])
        src = xin + (size_t)m * PIX * CIN;
        b   = m / TT;
        wg  = wsrc;
    }

    // ---- load input tile with halo, transposed to [ic][yy][xx] ----
    for (int i = tid; i < 3200; i += NTH) {
        int ic = i & 31, pos = i >> 5;        // 100 positions of 10x10 halo
        int yy = pos / 10, xx = pos - yy * 10;
        int gy = y0 + yy - 1, gx = x0t + xx - 1;
        float v = 0.0f;
        if ((unsigned)gy < (unsigned)HWD && (unsigned)gx < (unsigned)HWD)
            v = src[(gy * HWD + gx) * CIN + ic];
        in_s[ic * 100 + pos] = v;
    }

    const int pg  = tid >> 4, pc = tid & 15;
    const int py  = pg >> 1,  px0 = (pg & 1) * 4;
    const int oc0 = pc * 8;

    float acc[4][8];
    if (RECUR) {
        const float* Zt = g_Z + ((size_t)(t * BB + b) * PIX) * COUT;
        #pragma unroll
        for (int p = 0; p < 4; p++) {
            int pix = (y0 + py) * HWD + x0t + px0 + p;
            const float4* zp = (const float4*)(Zt + (size_t)pix * COUT + oc0);
            float4 a0 = zp[0], a1 = zp[1];
            acc[p][0] = a0.x; acc[p][1] = a0.y; acc[p][2] = a0.z; acc[p][3] = a0.w;
            acc[p][4] = a1.x; acc[p][5] = a1.y; acc[p][6] = a1.z; acc[p][7] = a1.w;
        }
    } else {
        float bv[8];
        #pragma unroll
        for (int q = 0; q < 8; q++) bv[q] = bias[oc0 + q];
        #pragma unroll
        for (int p = 0; p < 4; p++)
            #pragma unroll
            for (int q = 0; q < 8; q++) acc[p][q] = bv[q];
    }

    // ---- main loop: ky outer (stage 49KB of weights), then ic, kx ----
    for (int ky = 0; ky < 3; ky++) {
        __syncthreads();
        {
            const float4* wsrc4 = (const float4*)(wg + (size_t)ky * 12288);
            float4* wdst4 = (float4*)w_s;
            for (int i = tid; i < 3072; i += NTH) wdst4[i] = wsrc4[i];
        }
        __syncthreads();

        const float* irow = in_s + (py + ky) * 10 + px0;
        #pragma unroll 2
        for (int ic = 0; ic < 32; ic++) {
            float r[6];
            const float* ir = irow + ic * 100;
            #pragma unroll
            for (int j = 0; j < 6; j++) r[j] = ir[j];
            #pragma unroll
            for (int kx = 0; kx < 3; kx++) {
                const float4* wp = (const float4*)(w_s + (kx * 32 + ic) * COUT + oc0);
                float4 w0 = wp[0], w1 = wp[1];
                float w[8] = {w0.x, w0.y, w0.z, w0.w, w1.x, w1.y, w1.z, w1.w};
                #pragma unroll
                for (int p = 0; p < 4; p++) {
                    float rv = r[kx + p];
                    #pragma unroll
                    for (int q = 0; q < 8; q++)
                        acc[p][q] = fmaf(rv, w[q], acc[p][q]);
                }
            }
        }
    }

    if (!RECUR) {
        // store z-tile to Z[t][b]
        int m = blockIdx.y; int bb = m / TT, tt = m - bb * TT;
        float* Zt = g_Z + ((size_t)(tt * BB + bb) * PIX) * COUT;
        #pragma unroll
        for (int p = 0; p < 4; p++) {
            int pix = (y0 + py) * HWD + x0t + px0 + p;
            float4* zp = (float4*)(Zt + (size_t)pix * COUT + oc0);
            zp[0] = make_float4(acc[p][0], acc[p][1], acc[p][2], acc[p][3]);
            zp[1] = make_float4(acc[p][4], acc[p][5], acc[p][6], acc[p][7]);
        }
    } else {
        // exchange z through smem, then fused LSTM gate epilogue
        #pragma unroll
        for (int p = 0; p < 4; p++) {
            int lp = py * 8 + px0 + p;
            float4* zp = (float4*)(zs + lp * COUT + oc0);
            zp[0] = make_float4(acc[p][0], acc[p][1], acc[p][2], acc[p][3]);
            zp[1] = make_float4(acc[p][4], acc[p][5], acc[p][6], acc[p][7]);
        }
        __syncthreads();

        float* Hcur = g_H[t & 1];
        #pragma unroll
        for (int k = 0; k < 8; k++) {
            int idx = tid + k * NTH;          // 2048 (px,f) pairs
            int f  = idx & 31, lp = idx >> 5;
            float zi = zs[lp * COUT + f];
            float zf = zs[lp * COUT + 32 + f];
            float zc = zs[lp * COUT + 64 + f];
            float zo = zs[lp * COUT + 96 + f];
            int ly = lp >> 3, lx = lp & 7;
            int gy = y0 + ly, gx = x0t + lx;
            int hoff = (b * PIX + gy * HWD + gx) * CIN + f;
            float cold = g_C[hoff];
            float cn = hsig(zf) * cold + hsig(zi) * tanhf(zc);
            float hn = hsig(zo) * tanhf(cn);
            g_C[hoff]  = cn;
            Hcur[hoff] = hn;
            dout[(size_t)b * (TT * PIX * CIN) + (size_t)t * (PIX * CIN)
                 + (size_t)(gy * HWD + gx) * CIN + f] = hn;
        }
    }
}

// ---------------- launch ----------------
extern "C" void kernel_launch(void* const* d_in, const int* in_sizes, int n_in,
                              void* d_out, int out_size) {
    (void)in_sizes; (void)n_in; (void)out_size;
    const float* tensor = (const float*)d_in[0];   // (8,12,96,96,32)
    const float* Wx     = (const float*)d_in[1];   // (3,3,32,128)
    const float* Wh     = (const float*)d_in[2];   // (3,3,32,128)
    const float* bias   = (const float*)d_in[3];   // (128,)
    float* out = (float*)d_out;                    // (8,12,1,96,96,32) fp32

    const int SMEM_PRE = (3200 + 12288) * 4;          // 61952 B
    const int SMEM_REC = (3200 + 12288 + 8192) * 4;   // 94720 B
    cudaFuncSetAttribute((const void*)conv_kernel<false>,
                         cudaFuncAttributeMaxDynamicSharedMemorySize, SMEM_PRE);
    cudaFuncSetAttribute((const void*)conv_kernel<true>,
                         cudaFuncAttributeMaxDynamicSharedMemorySize, SMEM_REC);

    // 1) combined recurrent weights
    wcombine_kernel<<<(9 * CIN * COUT + NTH - 1) / NTH, NTH>>>(Wx, Wh);

    // 2) precompute Z[t] = conv(x_t, Wx) + b for all 96 (b,t) images in parallel
    conv_kernel<false><<<dim3(144, BB * TT), NTH, SMEM_PRE>>>(tensor, Wx, bias, nullptr, 0);

    // 3) step 0: h=c=0 -> pure pointwise gates on Z[0]
    gate0_kernel<<<(BB * PIX * CIN) / NTH, NTH>>>(out);

    // 4) steps 1..11: z = Z[t] + conv(h_{t-1}, Wc), fused gate update
    for (int t = 1; t < TT; t++)
        conv_kernel<true><<<dim3(144, BB), NTH, SMEM_REC>>>(nullptr, nullptr, nullptr, out, t);
}

// round 17
// speedup vs baseline: 1.0020x; 1.0007x over previous
#include <cuda_runtime.h>
#include <math.h>

// Problem constants
#define BB   8
#define TT   12
#define HWD  96
#define CIN  32
#define COUT 128
#define PIX  (HWD*HWD)          // 9216
#define NTH  256

// ---------------- device scratch (no allocs allowed) ----------------
// Z[t][b][pix][128] : precomputed conv(x_t, Wx) + bias, fp32
__device__ __align__(16) float g_Z[(size_t)TT * BB * PIX * COUT];   // ~453 MB
// h ping-pong buffers [2][b][pix][32]
__device__ __align__(16) float g_H[2][BB * PIX * CIN];
// c state (in-place per element is race-free: each element touched by one thread)
__device__ __align__(16) float g_C[BB * PIX * CIN];
// combined recurrent weight Wc = Wx + Wh : [3][3][32][128]
__device__ __align__(16) float g_Wc[9 * CIN * COUT];

__device__ __forceinline__ float hsig(float z) {
    return fminf(fmaxf(fmaf(z, 0.2f, 0.5f), 0.0f), 1.0f);
}

// ---------------- tiny kernel: Wc = Wx + Wh ----------------
__global__ void wcombine_kernel(const float* __restrict__ Wx,
                                const float* __restrict__ Wh) {
    int i = blockIdx.x * NTH + threadIdx.x;
    if (i < 9 * CIN * COUT) g_Wc[i] = Wx[i] + Wh[i];
}

// ---------------- step 0: gates on Z[0] with h=c=0 ----------------
__global__ void gate0_kernel(float* __restrict__ dout) {
    int idx = blockIdx.x * NTH + threadIdx.x;     // < BB*PIX*CIN
    int f    = idx & 31;
    int rest = idx >> 5;                           // b*PIX + pix
    int pix  = rest % PIX;
    int b    = rest / PIX;
    const float* Z0 = g_Z + ((size_t)b * PIX + pix) * COUT;
    float zi = Z0[f], zf = Z0[32 + f], zc = Z0[64 + f], zo = Z0[96 + f];
    float cn = hsig(zi) * tanhf(zc);               // f*0 + i*tanh(zc)
    float hn = hsig(zo) * tanhf(cn);
    int hoff = (b * PIX + pix) * CIN + f;
    g_C[hoff]    = cn;
    g_H[0][hoff] = hn;
    dout[(size_t)b * (TT * PIX * CIN) + (size_t)pix * CIN + f] = hn;  // t=0 slice
}

// ---------------- main conv kernel ----------------
// Block: 8x8 pixel tile x all 128 out channels. 256 threads:
//   thread = (pg = tid>>4 : 16 pixel groups of 4 px) x (pc = tid&15 : 16 oc groups of 8)
// smem: in_s[32][10][10] (transposed, halo) | w_s[3][32][128] (per-ky stage) | zs[64][128] (RECUR)
template<bool RECUR>
__global__ void __launch_bounds__(NTH, 2) conv_kernel(
    const float* __restrict__ xin,    // tensor base (precompute); unused if RECUR
    const float* __restrict__ wsrc,   // Wx (precompute); unused if RECUR (uses g_Wc)
    const float* __restrict__ bias,   // bias (precompute); unused if RECUR
    float* __restrict__ dout,         // output (RECUR); unused otherwise
    int t)                            // step (RECUR)
{
    extern __shared__ float smem[];
    float* in_s = smem;                       // 3200 floats
    float* w_s  = smem + 3200;                // 12288 floats
    float* zs   = smem + 3200 + 12288;        // 8192 floats (RECUR only)

    const int tid   = threadIdx.x;
    const int tileY = blockIdx.x / 12, tileX = blockIdx.x % 12;
    const int y0 = tileY * 8, x0t = tileX * 8;

    int b;
    const float* src;
    const float* wg;
    if (RECUR) {
        b   = blockIdx.y;
        src = g_H[(t - 1) & 1] + (size_t)b * PIX * CIN;   // read previous h
        wg  = g_Wc;
    } else {
        int m = blockIdx.y;                   // m = b*TT + t  (tensor layout [b][t])
        src = xin + (size_t)m * PIX * CIN;
        b   = m / TT;
        wg  = wsrc;
    }

    // ---- load input tile with halo, transposed to [ic][yy][xx] ----
    for (int i = tid; i < 3200; i += NTH) {
        int ic = i & 31, pos = i >> 5;        // 100 positions of 10x10 halo
        int yy = pos / 10, xx = pos - yy * 10;
        int gy = y0 + yy - 1, gx = x0t + xx - 1;
        float v = 0.0f;
        if ((unsigned)gy < (unsigned)HWD && (unsigned)gx < (unsigned)HWD)
            v = src[(gy * HWD + gx) * CIN + ic];
        in_s[ic * 100 + pos] = v;
    }

    const int pg  = tid >> 4, pc = tid & 15;
    const int py  = pg >> 1,  px0 = (pg & 1) * 4;
    const int oc0 = pc * 8;

    float acc[4][8];
    if (RECUR) {
        const float* Zt = g_Z + ((size_t)(t * BB + b) * PIX) * COUT;
        #pragma unroll
        for (int p = 0; p < 4; p++) {
            int pix = (y0 + py) * HWD + x0t + px0 + p;
            const float4* zp = (const float4*)(Zt + (size_t)pix * COUT + oc0);
            float4 a0 = zp[0], a1 = zp[1];
            acc[p][0] = a0.x; acc[p][1] = a0.y; acc[p][2] = a0.z; acc[p][3] = a0.w;
            acc[p][4] = a1.x; acc[p][5] = a1.y; acc[p][6] = a1.z; acc[p][7] = a1.w;
        }
    } else {
        float bv[8];
        #pragma unroll
        for (int q = 0; q < 8; q++) bv[q] = bias[oc0 + q];
        #pragma unroll
        for (int p = 0; p < 4; p++)
            #pragma unroll
            for (int q = 0; q < 8; q++) acc[p][q] = bv[q];
    }

    // ---- main loop: ky outer (stage 49KB of weights), then ic, kx ----
    for (int ky = 0; ky < 3; ky++) {
        __syncthreads();
        {
            const float4* wsrc4 = (const float4*)(wg + (size_t)ky * 12288);
            float4* wdst4 = (float4*)w_s;
            for (int i = tid; i < 3072; i += NTH) wdst4[i] = wsrc4[i];
        }
        __syncthreads();

        const float* irow = in_s + (py + ky) * 10 + px0;
        #pragma unroll 2
        for (int ic = 0; ic < 32; ic++) {
            float r[6];
            const float* ir = irow + ic * 100;
            #pragma unroll
            for (int j = 0; j < 6; j++) r[j] = ir[j];
            #pragma unroll
            for (int kx = 0; kx < 3; kx++) {
                const float4* wp = (const float4*)(w_s + (kx * 32 + ic) * COUT + oc0);
                float4 w0 = wp[0], w1 = wp[1];
                float w[8] = {w0.x, w0.y, w0.z, w0.w, w1.x, w1.y, w1.z, w1.w};
                #pragma unroll
                for (int p = 0; p < 4; p++) {
                    float rv = r[kx + p];
                    #pragma unroll
                    for (int q = 0; q < 8; q++)
                        acc[p][q] = fmaf(rv, w[q], acc[p][q]);
                }
            }
        }
    }

    if (!RECUR) {
        // store z-tile to Z[t][b]
        int m = blockIdx.y; int bb = m / TT, tt = m - bb * TT;
        float* Zt = g_Z + ((size_t)(tt * BB + bb) * PIX) * COUT;
        #pragma unroll
        for (int p = 0; p < 4; p++) {
            int pix = (y0 + py) * HWD + x0t + px0 + p;
            float4* zp = (float4*)(Zt + (size_t)pix * COUT + oc0);
            zp[0] = make_float4(acc[p][0], acc[p][1], acc[p][2], acc[p][3]);
            zp[1] = make_float4(acc[p][4], acc[p][5], acc[p][6], acc[p][7]);
        }
    } else {
        // exchange z through smem, then fused LSTM gate epilogue
        #pragma unroll
        for (int p = 0; p < 4; p++) {
            int lp = py * 8 + px0 + p;
            float4* zp = (float4*)(zs + lp * COUT + oc0);
            zp[0] = make_float4(acc[p][0], acc[p][1], acc[p][2], acc[p][3]);
            zp[1] = make_float4(acc[p][4], acc[p][5], acc[p][6], acc[p][7]);
        }
        __syncthreads();

        float* Hcur = g_H[t & 1];
        #pragma unroll
        for (int k = 0; k < 8; k++) {
            int idx = tid + k * NTH;          // 2048 (px,f) pairs
            int f  = idx & 31, lp = idx >> 5;
            float zi = zs[lp * COUT + f];
            float zf = zs[lp * COUT + 32 + f];
            float zc = zs[lp * COUT + 64 + f];
            float zo = zs[lp * COUT + 96 + f];
            int ly = lp >> 3, lx = lp & 7;
            int gy = y0 + ly, gx = x0t + lx;
            int hoff = (b * PIX + gy * HWD + gx) * CIN + f;
            float cold = g_C[hoff];
            float cn = hsig(zf) * cold + hsig(zi) * tanhf(zc);
            float hn = hsig(zo) * tanhf(cn);
            g_C[hoff]  = cn;
            Hcur[hoff] = hn;
            dout[(size_t)b * (TT * PIX * CIN) + (size_t)t * (PIX * CIN)
                 + (size_t)(gy * HWD + gx) * CIN + f] = hn;
        }
    }
}

// ---------------- launch ----------------
extern "C" void kernel_launch(void* const* d_in, const int* in_sizes, int n_in,
                              void* d_out, int out_size) {
    (void)in_sizes; (void)n_in; (void)out_size;
    const float* tensor = (const float*)d_in[0];   // (8,12,96,96,32)
    const float* Wx     = (const float*)d_in[1];   // (3,3,32,128)
    const float* Wh     = (const float*)d_in[2];   // (3,3,32,128)
    const float* bias   = (const float*)d_in[3];   // (128,)
    float* out = (float*)d_out;                    // (8,12,1,96,96,32) fp32

    const int SMEM_PRE = (3200 + 12288) * 4;          // 61952 B
    const int SMEM_REC = (3200 + 12288 + 8192) * 4;   // 94720 B
    cudaFuncSetAttribute((const void*)conv_kernel<false>,
                         cudaFuncAttributeMaxDynamicSharedMemorySize, SMEM_PRE);
    cudaFuncSetAttribute((const void*)conv_kernel<true>,
                         cudaFuncAttributeMaxDynamicSharedMemorySize, SMEM_REC);

    // 1) combined recurrent weights
    wcombine_kernel<<<(9 * CIN * COUT + NTH - 1) / NTH, NTH>>>(Wx, Wh);

    // 2) precompute Z[t] = conv(x_t, Wx) + b for all 96 (b,t) images in parallel
    conv_kernel<false><<<dim3(144, BB * TT), NTH, SMEM_PRE>>>(tensor, Wx, bias, nullptr, 0);

    // 3) step 0: h=c=0 -> pure pointwise gates on Z[0]
    gate0_kernel<<<(BB * PIX * CIN) / NTH, NTH>>>(out);

    // 4) steps 1..11: z = Z[t] + conv(h_{t-1}, Wc), fused gate update
    for (int t = 1; t < TT; t++)
        conv_kernel<true><<<dim3(144, BB), NTH, SMEM_REC>>>(nullptr, nullptr, nullptr, out, t);
}